// round 15
// baseline (speedup 1.0000x reference)
#include <cuda_runtime.h>
#include <math.h>
#include <stdint.h>

#define B_  8
#define N_  1024
#define D_  256
#define H_  4
#define DH_ 64
#define M_  512
#define EPS_ 1e-5f

// ---------------- scratch (device globals; no allocations allowed) ----------
__device__ float g_h[B_*N_*D_];                 // LN output
__device__ float g_qkv[B_*N_*3*D_];             // qkv
__device__ float g_o[B_*N_*D_];                 // attn out
__device__ float g_t1[B_*N_*M_];                // fc1/gelu out
__device__ float g_t2[B_*N_*M_];                // conv/bn/gelu out
__device__ float g_meanp2[128*256];             // colsum partials per row-tile
__device__ float g_gate[B_*D_];
__device__ int   g_cnt = 0;                     // last-block counter

__device__ __forceinline__ float gelu_exact(float v) {
    return 0.5f * v * (1.f + erff(v * 0.70710678118654752f));
}

__device__ __forceinline__ void mma_tf32(float& c0, float& c1, float& c2, float& c3,
                                         float a0, float a1, float a2, float a3,
                                         float b0, float b1)
{
    asm volatile(
        "mma.sync.aligned.m16n8k8.row.col.f32.tf32.tf32.f32 "
        "{%0,%1,%2,%3},{%4,%5,%6,%7},{%8,%9},{%0,%1,%2,%3};"
        : "+f"(c0), "+f"(c1), "+f"(c2), "+f"(c3)
        : "r"(__float_as_uint(a0)), "r"(__float_as_uint(a1)),
          "r"(__float_as_uint(a2)), "r"(__float_as_uint(a3)),
          "r"(__float_as_uint(b0)), "r"(__float_as_uint(b1)));
}

__device__ __forceinline__ void cp16(uint32_t dst, const void* src) {
    asm volatile("cp.async.cg.shared.global [%0], [%1], 16;" :: "r"(dst), "l"(src));
}
__device__ __forceinline__ void cp_commit() {
    asm volatile("cp.async.commit_group;" ::: "memory");
}
template<int N>
__device__ __forceinline__ void cp_wait() {
    asm volatile("cp.async.wait_group %0;" :: "n"(N) : "memory");
}
__device__ __forceinline__ uint32_t smem_u32(const void* p) {
    return (uint32_t)__cvta_generic_to_shared(p);
}

// ---------------- flash attention (split K/V waits) --------------------------
#define FBM 64
#define FBN 64

struct FlashSmem {
    float Q[FBM][68];
    float K[2][FBN][68];
    float V[2][FBN][72];
    float P[4][16][68];
};
#define FLASH_SMEM_BYTES ((int)sizeof(FlashSmem))

__global__ __launch_bounds__(128)
void flash_k(const float* __restrict__ qkv, float* __restrict__ Og)
{
    extern __shared__ float smem_raw[];
    FlashSmem& S = *(FlashSmem*)smem_raw;

    const int bh = blockIdx.z;
    const int b = bh >> 2, h = bh & 3;
    const int m0 = blockIdx.y * FBM;
    const int tid  = threadIdx.x;
    const int warp = tid >> 5, lane = tid & 31;
    const int gid  = lane >> 2, tig = lane & 3;

    const float* qb = qkv + ((size_t)b * N_) * (3*D_) + h * DH_;

    #pragma unroll
    for (int i = 0; i < 8; i++) {
        int v = tid + i * 128;
        int r = v >> 4, dq = v & 15;
        float4 t = *(const float4*)&qb[(size_t)(m0 + r) * (3*D_) + dq * 4];
        t.x *= 0.125f; t.y *= 0.125f; t.z *= 0.125f; t.w *= 0.125f;
        *(float4*)&S.Q[r][dq * 4] = t;
    }

    auto issueK = [&](int buf, int t) {
        const float* kb = qkv + ((size_t)b * N_ + t * FBN) * (3*D_) + D_ + h * DH_;
        #pragma unroll
        for (int i = 0; i < 8; i++) {
            int v = tid + i * 128;
            int r = v >> 4, dq = v & 15;
            cp16(smem_u32(&S.K[buf][r][dq * 4]), &kb[(size_t)r * (3*D_) + dq * 4]);
        }
    };
    auto issueV = [&](int buf, int t) {
        const float* vb = qkv + ((size_t)b * N_ + t * FBN) * (3*D_) + 2*D_ + h * DH_;
        #pragma unroll
        for (int i = 0; i < 8; i++) {
            int v = tid + i * 128;
            int r = v >> 4, dq = v & 15;
            cp16(smem_u32(&S.V[buf][r][dq * 4]), &vb[(size_t)r * (3*D_) + dq * 4]);
        }
    };

    float mr0 = -1e30f, mr1 = -1e30f, l0 = 0.f, l1 = 0.f;
    float o[8][4];
    #pragma unroll
    for (int nt = 0; nt < 8; nt++)
        #pragma unroll
        for (int c = 0; c < 4; c++) o[nt][c] = 0.f;

    const int qrow = warp * 16 + gid;
    const int NTiles = N_ / FBN;

    issueK(0, 0); cp_commit();
    issueV(0, 0); cp_commit();
    for (int t = 0; t < NTiles; t++) {
        int cur = t & 1;
        cp_wait<1>();
        __syncthreads();
        if (t + 1 < NTiles) issueK(cur ^ 1, t + 1);
        cp_commit();

        float s[8][4];
        #pragma unroll
        for (int nt = 0; nt < 8; nt++)
            #pragma unroll
            for (int c = 0; c < 4; c++) s[nt][c] = 0.f;

        #pragma unroll
        for (int ks = 0; ks < DH_; ks += 8) {
            float a0 = S.Q[qrow    ][ks + tig];
            float a1 = S.Q[qrow + 8][ks + tig];
            float a2 = S.Q[qrow    ][ks + tig + 4];
            float a3 = S.Q[qrow + 8][ks + tig + 4];
            #pragma unroll
            for (int nt = 0; nt < 8; nt++) {
                float b0 = S.K[cur][nt * 8 + gid][ks + tig];
                float b1 = S.K[cur][nt * 8 + gid][ks + tig + 4];
                mma_tf32(s[nt][0], s[nt][1], s[nt][2], s[nt][3],
                         a0, a1, a2, a3, b0, b1);
            }
        }

        float rm0 = -1e30f, rm1 = -1e30f;
        #pragma unroll
        for (int nt = 0; nt < 8; nt++) {
            rm0 = fmaxf(rm0, fmaxf(s[nt][0], s[nt][1]));
            rm1 = fmaxf(rm1, fmaxf(s[nt][2], s[nt][3]));
        }
        rm0 = fmaxf(rm0, __shfl_xor_sync(0xffffffff, rm0, 1));
        rm0 = fmaxf(rm0, __shfl_xor_sync(0xffffffff, rm0, 2));
        rm1 = fmaxf(rm1, __shfl_xor_sync(0xffffffff, rm1, 1));
        rm1 = fmaxf(rm1, __shfl_xor_sync(0xffffffff, rm1, 2));

        float mn0 = fmaxf(mr0, rm0), mn1 = fmaxf(mr1, rm1);
        float sc0 = __expf(mr0 - mn0), sc1 = __expf(mr1 - mn1);
        mr0 = mn0; mr1 = mn1;

        float rs0 = 0.f, rs1 = 0.f;
        #pragma unroll
        for (int nt = 0; nt < 8; nt++) {
            s[nt][0] = __expf(s[nt][0] - mn0);
            s[nt][1] = __expf(s[nt][1] - mn0);
            s[nt][2] = __expf(s[nt][2] - mn1);
            s[nt][3] = __expf(s[nt][3] - mn1);
            rs0 += s[nt][0] + s[nt][1];
            rs1 += s[nt][2] + s[nt][3];
        }
        rs0 += __shfl_xor_sync(0xffffffff, rs0, 1);
        rs0 += __shfl_xor_sync(0xffffffff, rs0, 2);
        rs1 += __shfl_xor_sync(0xffffffff, rs1, 1);
        rs1 += __shfl_xor_sync(0xffffffff, rs1, 2);
        l0 = l0 * sc0 + rs0;
        l1 = l1 * sc1 + rs1;

        #pragma unroll
        for (int nt = 0; nt < 8; nt++) {
            o[nt][0] *= sc0; o[nt][1] *= sc0;
            o[nt][2] *= sc1; o[nt][3] *= sc1;
        }

        cp_wait<1>();
        __syncthreads();
        if (t + 1 < NTiles) issueV(cur ^ 1, t + 1);
        cp_commit();

        #pragma unroll
        for (int nt = 0; nt < 8; nt++) {
            S.P[warp][gid    ][nt * 8 + tig * 2    ] = s[nt][0];
            S.P[warp][gid    ][nt * 8 + tig * 2 + 1] = s[nt][1];
            S.P[warp][gid + 8][nt * 8 + tig * 2    ] = s[nt][2];
            S.P[warp][gid + 8][nt * 8 + tig * 2 + 1] = s[nt][3];
        }
        __syncwarp();

        #pragma unroll
        for (int ks = 0; ks < FBN; ks += 8) {
            float a0 = S.P[warp][gid    ][ks + tig];
            float a1 = S.P[warp][gid + 8][ks + tig];
            float a2 = S.P[warp][gid    ][ks + tig + 4];
            float a3 = S.P[warp][gid + 8][ks + tig + 4];
            #pragma unroll
            for (int nt = 0; nt < 8; nt++) {
                float b0 = S.V[cur][ks + tig    ][nt * 8 + gid];
                float b1 = S.V[cur][ks + tig + 4][nt * 8 + gid];
                mma_tf32(o[nt][0], o[nt][1], o[nt][2], o[nt][3],
                         a0, a1, a2, a3, b0, b1);
            }
        }
        __syncwarp();
    }

    float inv0 = 1.f / l0, inv1 = 1.f / l1;
    int r0 = m0 + qrow;
    float* ob0 = Og + ((size_t)b * N_ + r0    ) * D_ + h * DH_;
    float* ob1 = Og + ((size_t)b * N_ + r0 + 8) * D_ + h * DH_;
    #pragma unroll
    for (int nt = 0; nt < 8; nt++) {
        int col = nt * 8 + tig * 2;
        *(float2*)&ob0[col] = make_float2(o[nt][0] * inv0, o[nt][1] * inv0);
        *(float2*)&ob1[col] = make_float2(o[nt][2] * inv1, o[nt][3] * inv1);
    }
}

// ---------------- big dense GEMM (tf32, multi-stage) --------------------------
template<int BM, int BN, int BK, int WSM, int WSN, int ACT, int STAGES>
__global__ __launch_bounds__(WSM*WSN*32)
void gemm7_k(const float* __restrict__ A, int lda,
             const float* __restrict__ Bm, int ldb,
             float* __restrict__ C, int ldc,
             const float* __restrict__ bias, int K)
{
    constexpr int NT = WSM * WSN * 32;
    constexpr int WM = BM / WSM, WN = BN / WSN;
    constexpr int MT = WM / 16, NTL = WN / 8;
    constexpr int SA = BK + 4;
    constexpr int SB = BN + 8;
    constexpr int LA = BM * BK / (4 * NT);
    constexpr int LB = BN * BK / (4 * NT);
    constexpr int KQ = BK / 4;

    extern __shared__ float smem[];
    float (*As)[BM][SA] = reinterpret_cast<float(*)[BM][SA]>(smem);
    float (*Bs)[BK][SB] = reinterpret_cast<float(*)[BK][SB]>(smem + STAGES * BM * SA);

    const int m0 = blockIdx.y * BM;
    const int n0 = blockIdx.x * BN;
    const int tid   = threadIdx.x;
    const int warp  = tid >> 5;
    const int lane  = tid & 31;
    const int gid   = lane >> 2;
    const int tig   = lane & 3;
    const int warpM = warp / WSN;
    const int warpN = warp % WSN;

    auto issue = [&](int buf, int k0) {
        #pragma unroll
        for (int i = 0; i < LA; i++) {
            int v = tid + i * NT;
            int m = v / KQ, kq = v % KQ;
            cp16(smem_u32(&As[buf][m][kq * 4]),
                 &A[(size_t)(m0 + m) * lda + k0 + kq * 4]);
        }
        #pragma unroll
        for (int i = 0; i < LB; i++) {
            int v = tid + i * NT;
            int nq = v % (BN / 4), k = v / (BN / 4);
            cp16(smem_u32(&Bs[buf][k][nq * 4]),
                 &Bm[(size_t)(k0 + k) * ldb + n0 + nq * 4]);
        }
    };

    float acc[MT][NTL][4];
    #pragma unroll
    for (int i = 0; i < MT; i++)
        #pragma unroll
        for (int j = 0; j < NTL; j++)
            #pragma unroll
            for (int c = 0; c < 4; c++) acc[i][j][c] = 0.f;

    const int NI = K / BK;
    #pragma unroll
    for (int s = 0; s < STAGES - 1; s++) { issue(s, s * BK); cp_commit(); }

    int cur = 0;
    for (int i = 0; i < NI; i++) {
        cp_wait<STAGES - 2>();
        __syncthreads();
        int nx = i + STAGES - 1;
        if (nx < NI) issue(nx % STAGES, nx * BK);
        cp_commit();

        #pragma unroll
        for (int ks = 0; ks < BK; ks += 8) {
            float af[MT][4], bf[NTL][2];
            #pragma unroll
            for (int mt = 0; mt < MT; mt++) {
                int rb0 = warpM * WM + mt * 16;
                af[mt][0] = As[cur][rb0 + gid    ][ks + tig];
                af[mt][1] = As[cur][rb0 + gid + 8][ks + tig];
                af[mt][2] = As[cur][rb0 + gid    ][ks + tig + 4];
                af[mt][3] = As[cur][rb0 + gid + 8][ks + tig + 4];
            }
            #pragma unroll
            for (int nt = 0; nt < NTL; nt++) {
                int cb0 = warpN * WN + nt * 8;
                bf[nt][0] = Bs[cur][ks + tig    ][cb0 + gid];
                bf[nt][1] = Bs[cur][ks + tig + 4][cb0 + gid];
            }
            #pragma unroll
            for (int mt = 0; mt < MT; mt++)
                #pragma unroll
                for (int nt = 0; nt < NTL; nt++)
                    mma_tf32(acc[mt][nt][0], acc[mt][nt][1],
                             acc[mt][nt][2], acc[mt][nt][3],
                             af[mt][0], af[mt][1], af[mt][2], af[mt][3],
                             bf[nt][0], bf[nt][1]);
        }
        cur++; if (cur == STAGES) cur = 0;
    }

    #pragma unroll
    for (int mt = 0; mt < MT; mt++) {
        int row = m0 + warpM * WM + mt * 16 + gid;
        #pragma unroll
        for (int nt = 0; nt < NTL; nt++) {
            int col = n0 + warpN * WN + nt * 8 + tig * 2;
            float v0 = acc[mt][nt][0];
            float v1 = acc[mt][nt][1];
            float v2 = acc[mt][nt][2];
            float v3 = acc[mt][nt][3];
            if (bias) {
                float b0v = bias[col], b1v = bias[col + 1];
                v0 += b0v; v1 += b1v; v2 += b0v; v3 += b1v;
            }
            if (ACT == 1) {
                v0 = gelu_exact(v0); v1 = gelu_exact(v1);
                v2 = gelu_exact(v2); v3 = gelu_exact(v3);
            }
            *(float2*)&C[(size_t)row * ldc + col]       = make_float2(v0, v1);
            *(float2*)&C[(size_t)(row + 8) * ldc + col] = make_float2(v2, v3);
        }
    }
}

constexpr int gemm7_smem(int BM, int BN, int BK, int S) {
    return (S * BM * (BK + 4) + S * BK * (BN + 8)) * 4;
}

// ---------------- thin GEMM v3: 64x128, BK=16, 256 thr ------------------------
// X(tile) = (GATED? gate*X : X) + A @ B + bias; colsum -> meanp2.
// Last CTA (threadfence+counter) computes the NEW gate into gateOut.
#define TSTG 3
constexpr int thin2_smem() {
    return (TSTG * 64 * 20 + TSTG * 16 * 136 + 64 * 132) * 4;   // 75264
}

template<int GATED>
__global__ __launch_bounds__(256)
void gemm_thin_k(const float* __restrict__ A, int lda,
                 const float* __restrict__ Bm, int ldb,
                 float* __restrict__ C, int ldc,
                 const float* __restrict__ bias, int K,
                 float* __restrict__ meanp2,
                 const float* __restrict__ gateIn,
                 const float* __restrict__ w1, const float* __restrict__ w2,
                 float* __restrict__ gateOut)
{
    constexpr int BM = 64, BN = 128, BK = 16;
    constexpr int MT = 2, NTL = 4;
    constexpr int SA = 20, SB = 136, SC = 132;

    extern __shared__ float smemf[];
    float (*As)[BM][SA] = reinterpret_cast<float(*)[BM][SA]>(smemf);
    float (*Bs)[BK][SB] = reinterpret_cast<float(*)[BK][SB]>(smemf + TSTG * BM * SA);
    float* Cs = smemf + TSTG * BM * SA + TSTG * BK * SB;
    __shared__ float scred[8][128];
    __shared__ float gg[128];
    __shared__ float mg[256];
    __shared__ float tg[64];
    __shared__ int is_last;

    const int m0 = blockIdx.y * BM;
    const int n0 = blockIdx.x * BN;
    const int tid   = threadIdx.x;
    const int warp  = tid >> 5;
    const int lane  = tid & 31;
    const int gid   = lane >> 2;
    const int tig   = lane & 3;
    const int warpM = warp >> 2;
    const int warpN = warp & 3;

    // prefetch C tile (residual) — first commit group
    #pragma unroll
    for (int i = 0; i < 8; i++) {
        int v = tid + i * 256;
        int r = v >> 5, c4 = v & 31;
        cp16(smem_u32(&Cs[r * SC + c4 * 4]),
             &C[(size_t)(m0 + r) * ldc + n0 + c4 * 4]);
    }
    cp_commit();

    if (GATED) {
        int batch = blockIdx.y >> 4;
        if (tid < 128) gg[tid] = gateIn[batch * D_ * 2 / 2 + 0];  // placeholder (overwritten below)
        if (tid < 128) gg[tid] = gateIn[batch * 256 + n0 + tid];
    }

    auto issue = [&](int buf, int k0) {
        {
            int m = tid >> 2, kq = tid & 3;
            cp16(smem_u32(&As[buf][m][kq * 4]),
                 &A[(size_t)(m0 + m) * lda + k0 + kq * 4]);
        }
        #pragma unroll
        for (int i = 0; i < 2; i++) {
            int v = tid + i * 256;
            int k = v >> 5, nq = v & 31;
            cp16(smem_u32(&Bs[buf][k][nq * 4]),
                 &Bm[(size_t)(k0 + k) * ldb + n0 + nq * 4]);
        }
    };

    float acc[MT][NTL][4];
    #pragma unroll
    for (int i = 0; i < MT; i++)
        #pragma unroll
        for (int j = 0; j < NTL; j++)
            #pragma unroll
            for (int c = 0; c < 4; c++) acc[i][j][c] = 0.f;

    const int NI = K / BK;
    #pragma unroll
    for (int s = 0; s < TSTG - 1; s++) { issue(s, s * BK); cp_commit(); }

    int cur = 0;
    for (int i = 0; i < NI; i++) {
        cp_wait<TSTG - 2>();
        __syncthreads();
        int nx = i + TSTG - 1;
        if (nx < NI) issue(nx % TSTG, nx * BK);
        cp_commit();

        #pragma unroll
        for (int ks = 0; ks < BK; ks += 8) {
            float af[MT][4], bf[NTL][2];
            #pragma unroll
            for (int mt = 0; mt < MT; mt++) {
                int rb0 = warpM * 32 + mt * 16;
                af[mt][0] = As[cur][rb0 + gid    ][ks + tig];
                af[mt][1] = As[cur][rb0 + gid + 8][ks + tig];
                af[mt][2] = As[cur][rb0 + gid    ][ks + tig + 4];
                af[mt][3] = As[cur][rb0 + gid + 8][ks + tig + 4];
            }
            #pragma unroll
            for (int nt = 0; nt < NTL; nt++) {
                int cb0 = warpN * 32 + nt * 8;
                bf[nt][0] = Bs[cur][ks + tig    ][cb0 + gid];
                bf[nt][1] = Bs[cur][ks + tig + 4][cb0 + gid];
            }
            #pragma unroll
            for (int mt = 0; mt < MT; mt++)
                #pragma unroll
                for (int nt = 0; nt < NTL; nt++)
                    mma_tf32(acc[mt][nt][0], acc[mt][nt][1],
                             acc[mt][nt][2], acc[mt][nt][3],
                             af[mt][0], af[mt][1], af[mt][2], af[mt][3],
                             bf[nt][0], bf[nt][1]);
        }
        cur++; if (cur == TSTG) cur = 0;
    }

    // stage acc + bias + (gated) residual into Cs
    #pragma unroll
    for (int mt = 0; mt < MT; mt++) {
        int lr = warpM * 32 + mt * 16 + gid;
        #pragma unroll
        for (int nt = 0; nt < NTL; nt++) {
            int lc = warpN * 32 + nt * 8 + tig * 2;
            float b0v = bias[n0 + lc], b1v = bias[n0 + lc + 1];
            float2 c0 = *(float2*)&Cs[lr * SC + lc];
            float2 c1 = *(float2*)&Cs[(lr + 8) * SC + lc];
            if (GATED) {
                float g0 = gg[lc], g1 = gg[lc + 1];
                c0.x *= g0; c0.y *= g1; c1.x *= g0; c1.y *= g1;
            }
            *(float2*)&Cs[lr * SC + lc] =
                make_float2(acc[mt][nt][0] + b0v + c0.x, acc[mt][nt][1] + b1v + c0.y);
            *(float2*)&Cs[(lr + 8) * SC + lc] =
                make_float2(acc[mt][nt][2] + b0v + c1.x, acc[mt][nt][3] + b1v + c1.y);
        }
    }
    __syncthreads();

    // coalesced float4 writeback + column partial sums
    int c4 = tid & 31, rg = tid >> 5;
    float cs0 = 0.f, cs1 = 0.f, cs2 = 0.f, cs3 = 0.f;
    #pragma unroll
    for (int i = 0; i < 8; i++) {
        int r = rg * 8 + i;
        float4 t = *(float4*)&Cs[r * SC + c4 * 4];
        cs0 += t.x; cs1 += t.y; cs2 += t.z; cs3 += t.w;
        *(float4*)&C[(size_t)(m0 + r) * ldc + n0 + c4 * 4] = t;
    }
    *(float4*)&scred[rg][c4 * 4] = make_float4(cs0, cs1, cs2, cs3);
    __syncthreads();
    if (tid < 128) {
        float s = 0.f;
        #pragma unroll
        for (int g = 0; g < 8; g++) s += scred[g][tid];
        meanp2[(size_t)blockIdx.y * 256 + n0 + tid] = s;
    }

    // ---- last-block: compute new gate into gateOut ----
    __threadfence();
    __syncthreads();
    if (tid == 0) {
        int prev = atomicAdd(&g_cnt, 1);
        is_last = (prev == (int)(gridDim.x * gridDim.y) - 1) ? 1 : 0;
    }
    __syncthreads();
    if (is_last) {
        for (int b = 0; b < B_; b++) {
            float acc0 = 0.f;
            #pragma unroll
            for (int i = 0; i < 16; i++)
                acc0 += meanp2[((size_t)(b * 16 + i)) * 256 + tid];
            mg[tid] = acc0 * (1.f / N_);
            __syncthreads();
            if (tid < 64) {
                float a = 0.f;
                #pragma unroll 8
                for (int d = 0; d < D_; d++) a += mg[d] * w1[d * 64 + tid];
                tg[tid] = fmaxf(a, 0.f);
            }
            __syncthreads();
            float a = 0.f;
            #pragma unroll 8
            for (int j = 0; j < 64; j++) a += tg[j] * w2[j * D_ + tid];
            gateOut[b * D_ + tid] = 1.f / (1.f + expf(-a));
            __syncthreads();
        }
        if (tid == 0) atomicExch(&g_cnt, 0);
    }
}

// ---------------- fused copy + layernorm (float4, 4 rows/CTA) ----------------
__global__ void copy_ln_k(const float4* __restrict__ xin, float4* __restrict__ X,
                          const float* __restrict__ g, const float* __restrict__ b,
                          float4* __restrict__ out)
{
    int tid = threadIdx.x;
    int rib = tid >> 6, t64 = tid & 63;
    int row = blockIdx.x * 4 + rib;
    int idx = row * 64 + t64;
    int lane = tid & 31, wir = (tid >> 5) & 1;
    __shared__ float r1[4][2], r2[4][2];

    float4 v = xin[idx];
    X[idx] = v;
    float s  = v.x + v.y + v.z + v.w;
    float s2 = v.x*v.x + v.y*v.y + v.z*v.z + v.w*v.w;
    #pragma unroll
    for (int m = 16; m > 0; m >>= 1) {
        s  += __shfl_xor_sync(0xffffffff, s, m);
        s2 += __shfl_xor_sync(0xffffffff, s2, m);
    }
    if (lane == 0) { r1[rib][wir] = s; r2[rib][wir] = s2; }
    __syncthreads();
    float ts = r1[rib][0] + r1[rib][1], ts2 = r2[rib][0] + r2[rib][1];
    float mu = ts * (1.f / D_);
    float var = ts2 * (1.f / D_) - mu * mu;
    float rs = rsqrtf(var + EPS_);
    float4 gg = *(const float4*)&g[t64 * 4];
    float4 bb = *(const float4*)&b[t64 * 4];
    float4 o;
    o.x = (v.x - mu) * rs * gg.x + bb.x;
    o.y = (v.y - mu) * rs * gg.y + bb.y;
    o.z = (v.z - mu) * rs * gg.z + bb.z;
    o.w = (v.w - mu) * rs * gg.w + bb.w;
    out[idx] = o;
}

// ------- fused (virtual) scale + layernorm: reads gate, does NOT write X -----
__global__ void scale_ln_k(const float4* __restrict__ X, const float* __restrict__ gate,
                           const float* __restrict__ g, const float* __restrict__ b,
                           float4* __restrict__ out)
{
    int tid = threadIdx.x;
    int rib = tid >> 6, t64 = tid & 63;
    int row = blockIdx.x * 4 + rib;
    int bbatch = row >> 10;
    int idx = row * 64 + t64;
    int lane = tid & 31, wir = (tid >> 5) & 1;
    __shared__ float r1[4][2], r2[4][2];

    float4 gv = *(const float4*)&gate[bbatch * D_ + t64 * 4];
    float4 v = X[idx];
    v.x *= gv.x; v.y *= gv.y; v.z *= gv.z; v.w *= gv.w;
    float s  = v.x + v.y + v.z + v.w;
    float s2 = v.x*v.x + v.y*v.y + v.z*v.z + v.w*v.w;
    #pragma unroll
    for (int m = 16; m > 0; m >>= 1) {
        s  += __shfl_xor_sync(0xffffffff, s, m);
        s2 += __shfl_xor_sync(0xffffffff, s2, m);
    }
    if (lane == 0) { r1[rib][wir] = s; r2[rib][wir] = s2; }
    __syncthreads();
    float ts = r1[rib][0] + r1[rib][1], ts2 = r2[rib][0] + r2[rib][1];
    float mu = ts * (1.f / D_);
    float var = ts2 * (1.f / D_) - mu * mu;
    float rs = rsqrtf(var + EPS_);
    float4 gg = *(const float4*)&g[t64 * 4];
    float4 bb = *(const float4*)&b[t64 * 4];
    float4 o;
    o.x = (v.x - mu) * rs * gg.x + bb.x;
    o.y = (v.y - mu) * rs * gg.y + bb.y;
    o.z = (v.z - mu) * rs * gg.z + bb.z;
    o.w = (v.w - mu) * rs * gg.w + bb.w;
    out[idx] = o;
}

__global__ void scale_k(float4* __restrict__ x, const float* __restrict__ gate)
{
    int idx = blockIdx.x * 256 + threadIdx.x;
    int d4 = idx & (D_ / 4 - 1);
    int b = idx / (N_ * D_ / 4);
    const float4 gv = *(const float4*)&gate[b * D_ + d4 * 4];
    float4 v = x[idx];
    v.x *= gv.x; v.y *= gv.y; v.z *= gv.z; v.w *= gv.w;
    x[idx] = v;
}

// depthwise 1x3 conv + center-tap + BN(eval) + exact gelu (float4)
__global__ void conv_k(const float4* __restrict__ y, const float* __restrict__ wh,
                       const float* __restrict__ bh, const float* __restrict__ wv,
                       const float* __restrict__ bv, const float* __restrict__ bng,
                       const float* __restrict__ bnb, const float* __restrict__ bnm,
                       const float* __restrict__ bnv, float4* __restrict__ out)
{
    int idx = blockIdx.x * 256 + threadIdx.x;
    int m4 = idx & (M_ / 4 - 1);
    int n = (idx / (M_ / 4)) & (N_ - 1);
    int m = m4 * 4;
    float4 y0 = y[idx];
    float4 ym = (n > 0)      ? y[idx - M_ / 4] : make_float4(0.f, 0.f, 0.f, 0.f);
    float4 yp = (n < N_ - 1) ? y[idx + M_ / 4] : make_float4(0.f, 0.f, 0.f, 0.f);
    float r[4];
    float y0a[4] = {y0.x, y0.y, y0.z, y0.w};
    float yma[4] = {ym.x, ym.y, ym.z, ym.w};
    float ypa[4] = {yp.x, yp.y, yp.z, yp.w};
    #pragma unroll
    for (int j = 0; j < 4; j++) {
        int mm = m + j;
        float ch = wh[mm * 3 + 0] * yma[j] + wh[mm * 3 + 1] * y0a[j]
                 + wh[mm * 3 + 2] * ypa[j] + bh[mm];
        float cv = wv[mm * 3 + 1] * y0a[j] + bv[mm];
        float zz = ch + cv;
        zz = (zz - bnm[mm]) * rsqrtf(bnv[mm] + EPS_) * bng[mm] + bnb[mm];
        r[j] = gelu_exact(zz);
    }
    out[idx] = make_float4(r[0], r[1], r[2], r[3]);
}

// ---------------- driver -----------------------------------------------------
extern "C" void kernel_launch(void* const* d_in, const int* in_sizes, int n_in,
                              void* d_out, int out_size)
{
    const float* x_in  = (const float*)d_in[0];
    const float* ln1_g = (const float*)d_in[1];
    const float* ln1_b = (const float*)d_in[2];
    const float* w_qkv = (const float*)d_in[3];
    const float* w_out = (const float*)d_in[4];
    const float* b_out = (const float*)d_in[5];
    const float* ln2_g = (const float*)d_in[6];
    const float* ln2_b = (const float*)d_in[7];
    const float* w_fc1 = (const float*)d_in[8];
    const float* b_fc1 = (const float*)d_in[9];
    const float* wh    = (const float*)d_in[10];
    const float* bh    = (const float*)d_in[11];
    const float* wv    = (const float*)d_in[12];
    const float* bv    = (const float*)d_in[13];
    const float* bn_g  = (const float*)d_in[14];
    const float* bn_b  = (const float*)d_in[15];
    const float* bn_m  = (const float*)d_in[16];
    const float* bn_v  = (const float*)d_in[17];
    const float* w_fc2 = (const float*)d_in[18];
    const float* b_fc2 = (const float*)d_in[19];
    const float* ls_w1 = (const float*)d_in[20];
    const float* ls_w2 = (const float*)d_in[21];

    float *ph, *pqkv, *po, *pt1, *pt2, *pmeanp2, *pgate;
    cudaGetSymbolAddress((void**)&ph,      g_h);
    cudaGetSymbolAddress((void**)&pqkv,    g_qkv);
    cudaGetSymbolAddress((void**)&po,      g_o);
    cudaGetSymbolAddress((void**)&pt1,     g_t1);
    cudaGetSymbolAddress((void**)&pt2,     g_t2);
    cudaGetSymbolAddress((void**)&pmeanp2, g_meanp2);
    cudaGetSymbolAddress((void**)&pgate,   g_gate);

    constexpr int SM_BIG  = gemm7_smem(128, 128, 16, 3);   // 56832
    constexpr int SM_THIN = thin2_smem();                  // 75264

    cudaFuncSetAttribute(flash_k, cudaFuncAttributeMaxDynamicSharedMemorySize,
                         FLASH_SMEM_BYTES);
    cudaFuncSetAttribute(gemm7_k<128,128,16,2,4,0,3>,
                         cudaFuncAttributeMaxDynamicSharedMemorySize, SM_BIG);
    cudaFuncSetAttribute(gemm7_k<128,128,16,2,4,1,3>,
                         cudaFuncAttributeMaxDynamicSharedMemorySize, SM_BIG);
    cudaFuncSetAttribute(gemm_thin_k<0>,
                         cudaFuncAttributeMaxDynamicSharedMemorySize, SM_THIN);
    cudaFuncSetAttribute(gemm_thin_k<1>,
                         cudaFuncAttributeMaxDynamicSharedMemorySize, SM_THIN);

    float* X = (float*)d_out;
    const int ROWS = B_ * N_;   // 8192

    for (int l = 0; l < 2; l++) {
        const float* w_qkv_l = w_qkv + (size_t)l * D_ * 3 * D_;
        const float* w_out_l = w_out + (size_t)l * D_ * D_;
        const float* b_out_l = b_out + (size_t)l * D_;
        const float* w_fc1_l = w_fc1 + (size_t)l * D_ * M_;
        const float* b_fc1_l = b_fc1 + (size_t)l * M_;
        const float* w_fc2_l = w_fc2 + (size_t)l * M_ * D_;
        const float* b_fc2_l = b_fc2 + (size_t)l * D_;
        const float* w1_l    = ls_w1 + (size_t)l * D_ * (D_/4);
        const float* w2_l    = ls_w2 + (size_t)l * (D_/4) * D_;

        // --- MHSA ---  (h = LN1(X); layer 0 fuses the initial copy)
        if (l == 0)
            copy_ln_k<<<ROWS/4, 256>>>((const float4*)x_in, (float4*)X,
                                       ln1_g, ln1_b, (float4*)ph);

        // qkv = h @ w_qkv
        gemm7_k<128,128,16,2,4,0,3><<<dim3((3*D_)/128, ROWS/128, 1), 256, SM_BIG>>>(
            ph, D_, w_qkv_l, 3*D_, pqkv, 3*D_, nullptr, D_);

        // fused attention
        flash_k<<<dim3(1, N_/FBM, B_*H_), 128, FLASH_SMEM_BYTES>>>(pqkv, po);

        // lsrc #1: X = (gate_prev * X) + o@w_out + b_out; last CTA -> new gate
        if (l == 0)
            gemm_thin_k<0><<<dim3(D_/128, ROWS/64, 1), 256, SM_THIN>>>(
                po, D_, w_out_l, D_, X, D_, b_out_l, D_, pmeanp2,
                nullptr, w1_l, w2_l, pgate);
        else
            gemm_thin_k<1><<<dim3(D_/128, ROWS/64, 1), 256, SM_THIN>>>(
                po, D_, w_out_l, D_, X, D_, b_out_l, D_, pmeanp2,
                pgate, w1_l, w2_l, pgate);

        // h = LN2(gate * X)   (X stays unscaled in memory)
        scale_ln_k<<<ROWS/4, 256>>>((const float4*)X, pgate,
                                    ln2_g + l * D_, ln2_b + l * D_, (float4*)ph);

        // --- MLP ---
        gemm7_k<128,128,16,2,4,1,3><<<dim3(M_/128, ROWS/128, 1), 256, SM_BIG>>>(
            ph, D_, w_fc1_l, M_, pt1, M_, b_fc1_l, D_);

        conv_k<<<(B_*N_*M_)/1024, 256>>>(
            (const float4*)pt1, wh + (size_t)l*M_*3, bh + (size_t)l*M_,
            wv + (size_t)l*M_*3, bv + (size_t)l*M_,
            bn_g + (size_t)l*M_, bn_b + (size_t)l*M_,
            bn_m + (size_t)l*M_, bn_v + (size_t)l*M_, (float4*)pt2);

        // lsrc #2: X = (gate * X) + t2@w_fc2 + b_fc2; last CTA -> new gate
        gemm_thin_k<1><<<dim3(D_/128, ROWS/64, 1), 256, SM_THIN>>>(
            pt2, M_, w_fc2_l, D_, X, D_, b_fc2_l, M_, pmeanp2,
            pgate, w1_l, w2_l, pgate);

        if (l + 1 < 2)
            scale_ln_k<<<ROWS/4, 256>>>((const float4*)X, pgate,
                                        ln1_g + (l+1) * D_, ln1_b + (l+1) * D_,
                                        (float4*)ph);
        else
            scale_k<<<(B_*N_*D_)/1024, 256>>>((float4*)X, pgate);
    }
}

// round 16
// speedup vs baseline: 1.4654x; 1.4654x over previous
#include <cuda_runtime.h>
#include <math.h>
#include <stdint.h>

#define B_  8
#define N_  1024
#define D_  256
#define H_  4
#define DH_ 64
#define M_  512
#define EPS_ 1e-5f

// ---------------- scratch (device globals; no allocations allowed) ----------
__device__ float g_h[B_*N_*D_];                 // LN output
__device__ float g_qkv[B_*N_*3*D_];             // qkv
__device__ float g_o[B_*N_*D_];                 // attn out
__device__ float g_t1[B_*N_*M_];                // fc1/gelu out
__device__ float g_t2[B_*N_*M_];                // conv/bn/gelu out
__device__ float g_meanp2[128*256];             // colsum partials per row-tile
__device__ float g_gate[B_*D_];

__device__ __forceinline__ float gelu_exact(float v) {
    return 0.5f * v * (1.f + erff(v * 0.70710678118654752f));
}

__device__ __forceinline__ void mma_tf32(float& c0, float& c1, float& c2, float& c3,
                                         float a0, float a1, float a2, float a3,
                                         float b0, float b1)
{
    asm volatile(
        "mma.sync.aligned.m16n8k8.row.col.f32.tf32.tf32.f32 "
        "{%0,%1,%2,%3},{%4,%5,%6,%7},{%8,%9},{%0,%1,%2,%3};"
        : "+f"(c0), "+f"(c1), "+f"(c2), "+f"(c3)
        : "r"(__float_as_uint(a0)), "r"(__float_as_uint(a1)),
          "r"(__float_as_uint(a2)), "r"(__float_as_uint(a3)),
          "r"(__float_as_uint(b0)), "r"(__float_as_uint(b1)));
}

__device__ __forceinline__ void cp16(uint32_t dst, const void* src) {
    asm volatile("cp.async.cg.shared.global [%0], [%1], 16;" :: "r"(dst), "l"(src));
}
__device__ __forceinline__ void cp_commit() {
    asm volatile("cp.async.commit_group;" ::: "memory");
}
template<int N>
__device__ __forceinline__ void cp_wait() {
    asm volatile("cp.async.wait_group %0;" :: "n"(N) : "memory");
}
__device__ __forceinline__ uint32_t smem_u32(const void* p) {
    return (uint32_t)__cvta_generic_to_shared(p);
}

// ---------------- flash attention (split K/V waits) --------------------------
#define FBM 64
#define FBN 64

struct FlashSmem {
    float Q[FBM][68];
    float K[2][FBN][68];
    float V[2][FBN][72];
    float P[4][16][68];
};
#define FLASH_SMEM_BYTES ((int)sizeof(FlashSmem))

__global__ __launch_bounds__(128)
void flash_k(const float* __restrict__ qkv, float* __restrict__ Og)
{
    extern __shared__ float smem_raw[];
    FlashSmem& S = *(FlashSmem*)smem_raw;

    const int bh = blockIdx.z;
    const int b = bh >> 2, h = bh & 3;
    const int m0 = blockIdx.y * FBM;
    const int tid  = threadIdx.x;
    const int warp = tid >> 5, lane = tid & 31;
    const int gid  = lane >> 2, tig = lane & 3;

    const float* qb = qkv + ((size_t)b * N_) * (3*D_) + h * DH_;

    #pragma unroll
    for (int i = 0; i < 8; i++) {
        int v = tid + i * 128;
        int r = v >> 4, dq = v & 15;
        float4 t = *(const float4*)&qb[(size_t)(m0 + r) * (3*D_) + dq * 4];
        t.x *= 0.125f; t.y *= 0.125f; t.z *= 0.125f; t.w *= 0.125f;
        *(float4*)&S.Q[r][dq * 4] = t;
    }

    auto issueK = [&](int buf, int t) {
        const float* kb = qkv + ((size_t)b * N_ + t * FBN) * (3*D_) + D_ + h * DH_;
        #pragma unroll
        for (int i = 0; i < 8; i++) {
            int v = tid + i * 128;
            int r = v >> 4, dq = v & 15;
            cp16(smem_u32(&S.K[buf][r][dq * 4]), &kb[(size_t)r * (3*D_) + dq * 4]);
        }
    };
    auto issueV = [&](int buf, int t) {
        const float* vb = qkv + ((size_t)b * N_ + t * FBN) * (3*D_) + 2*D_ + h * DH_;
        #pragma unroll
        for (int i = 0; i < 8; i++) {
            int v = tid + i * 128;
            int r = v >> 4, dq = v & 15;
            cp16(smem_u32(&S.V[buf][r][dq * 4]), &vb[(size_t)r * (3*D_) + dq * 4]);
        }
    };

    float mr0 = -1e30f, mr1 = -1e30f, l0 = 0.f, l1 = 0.f;
    float o[8][4];
    #pragma unroll
    for (int nt = 0; nt < 8; nt++)
        #pragma unroll
        for (int c = 0; c < 4; c++) o[nt][c] = 0.f;

    const int qrow = warp * 16 + gid;
    const int NTiles = N_ / FBN;

    issueK(0, 0); cp_commit();
    issueV(0, 0); cp_commit();
    for (int t = 0; t < NTiles; t++) {
        int cur = t & 1;
        cp_wait<1>();
        __syncthreads();
        if (t + 1 < NTiles) issueK(cur ^ 1, t + 1);
        cp_commit();

        float s[8][4];
        #pragma unroll
        for (int nt = 0; nt < 8; nt++)
            #pragma unroll
            for (int c = 0; c < 4; c++) s[nt][c] = 0.f;

        #pragma unroll
        for (int ks = 0; ks < DH_; ks += 8) {
            float a0 = S.Q[qrow    ][ks + tig];
            float a1 = S.Q[qrow + 8][ks + tig];
            float a2 = S.Q[qrow    ][ks + tig + 4];
            float a3 = S.Q[qrow + 8][ks + tig + 4];
            #pragma unroll
            for (int nt = 0; nt < 8; nt++) {
                float b0 = S.K[cur][nt * 8 + gid][ks + tig];
                float b1 = S.K[cur][nt * 8 + gid][ks + tig + 4];
                mma_tf32(s[nt][0], s[nt][1], s[nt][2], s[nt][3],
                         a0, a1, a2, a3, b0, b1);
            }
        }

        float rm0 = -1e30f, rm1 = -1e30f;
        #pragma unroll
        for (int nt = 0; nt < 8; nt++) {
            rm0 = fmaxf(rm0, fmaxf(s[nt][0], s[nt][1]));
            rm1 = fmaxf(rm1, fmaxf(s[nt][2], s[nt][3]));
        }
        rm0 = fmaxf(rm0, __shfl_xor_sync(0xffffffff, rm0, 1));
        rm0 = fmaxf(rm0, __shfl_xor_sync(0xffffffff, rm0, 2));
        rm1 = fmaxf(rm1, __shfl_xor_sync(0xffffffff, rm1, 1));
        rm1 = fmaxf(rm1, __shfl_xor_sync(0xffffffff, rm1, 2));

        float mn0 = fmaxf(mr0, rm0), mn1 = fmaxf(mr1, rm1);
        float sc0 = __expf(mr0 - mn0), sc1 = __expf(mr1 - mn1);
        mr0 = mn0; mr1 = mn1;

        float rs0 = 0.f, rs1 = 0.f;
        #pragma unroll
        for (int nt = 0; nt < 8; nt++) {
            s[nt][0] = __expf(s[nt][0] - mn0);
            s[nt][1] = __expf(s[nt][1] - mn0);
            s[nt][2] = __expf(s[nt][2] - mn1);
            s[nt][3] = __expf(s[nt][3] - mn1);
            rs0 += s[nt][0] + s[nt][1];
            rs1 += s[nt][2] + s[nt][3];
        }
        rs0 += __shfl_xor_sync(0xffffffff, rs0, 1);
        rs0 += __shfl_xor_sync(0xffffffff, rs0, 2);
        rs1 += __shfl_xor_sync(0xffffffff, rs1, 1);
        rs1 += __shfl_xor_sync(0xffffffff, rs1, 2);
        l0 = l0 * sc0 + rs0;
        l1 = l1 * sc1 + rs1;

        #pragma unroll
        for (int nt = 0; nt < 8; nt++) {
            o[nt][0] *= sc0; o[nt][1] *= sc0;
            o[nt][2] *= sc1; o[nt][3] *= sc1;
        }

        cp_wait<1>();
        __syncthreads();
        if (t + 1 < NTiles) issueV(cur ^ 1, t + 1);
        cp_commit();

        #pragma unroll
        for (int nt = 0; nt < 8; nt++) {
            S.P[warp][gid    ][nt * 8 + tig * 2    ] = s[nt][0];
            S.P[warp][gid    ][nt * 8 + tig * 2 + 1] = s[nt][1];
            S.P[warp][gid + 8][nt * 8 + tig * 2    ] = s[nt][2];
            S.P[warp][gid + 8][nt * 8 + tig * 2 + 1] = s[nt][3];
        }
        __syncwarp();

        #pragma unroll
        for (int ks = 0; ks < FBN; ks += 8) {
            float a0 = S.P[warp][gid    ][ks + tig];
            float a1 = S.P[warp][gid + 8][ks + tig];
            float a2 = S.P[warp][gid    ][ks + tig + 4];
            float a3 = S.P[warp][gid + 8][ks + tig + 4];
            #pragma unroll
            for (int nt = 0; nt < 8; nt++) {
                float b0 = S.V[cur][ks + tig    ][nt * 8 + gid];
                float b1 = S.V[cur][ks + tig + 4][nt * 8 + gid];
                mma_tf32(o[nt][0], o[nt][1], o[nt][2], o[nt][3],
                         a0, a1, a2, a3, b0, b1);
            }
        }
        __syncwarp();
    }

    float inv0 = 1.f / l0, inv1 = 1.f / l1;
    int r0 = m0 + qrow;
    float* ob0 = Og + ((size_t)b * N_ + r0    ) * D_ + h * DH_;
    float* ob1 = Og + ((size_t)b * N_ + r0 + 8) * D_ + h * DH_;
    #pragma unroll
    for (int nt = 0; nt < 8; nt++) {
        int col = nt * 8 + tig * 2;
        *(float2*)&ob0[col] = make_float2(o[nt][0] * inv0, o[nt][1] * inv0);
        *(float2*)&ob1[col] = make_float2(o[nt][2] * inv1, o[nt][3] * inv1);
    }
}

// ---------------- big dense GEMM (tf32, multi-stage) --------------------------
template<int BM, int BN, int BK, int WSM, int WSN, int ACT, int STAGES>
__global__ __launch_bounds__(WSM*WSN*32)
void gemm7_k(const float* __restrict__ A, int lda,
             const float* __restrict__ Bm, int ldb,
             float* __restrict__ C, int ldc,
             const float* __restrict__ bias, int K)
{
    constexpr int NT = WSM * WSN * 32;
    constexpr int WM = BM / WSM, WN = BN / WSN;
    constexpr int MT = WM / 16, NTL = WN / 8;
    constexpr int SA = BK + 4;
    constexpr int SB = BN + 8;
    constexpr int LA = BM * BK / (4 * NT);
    constexpr int LB = BN * BK / (4 * NT);
    constexpr int KQ = BK / 4;

    extern __shared__ float smem[];
    float (*As)[BM][SA] = reinterpret_cast<float(*)[BM][SA]>(smem);
    float (*Bs)[BK][SB] = reinterpret_cast<float(*)[BK][SB]>(smem + STAGES * BM * SA);

    const int m0 = blockIdx.y * BM;
    const int n0 = blockIdx.x * BN;
    const int tid   = threadIdx.x;
    const int warp  = tid >> 5;
    const int lane  = tid & 31;
    const int gid   = lane >> 2;
    const int tig   = lane & 3;
    const int warpM = warp / WSN;
    const int warpN = warp % WSN;

    auto issue = [&](int buf, int k0) {
        #pragma unroll
        for (int i = 0; i < LA; i++) {
            int v = tid + i * NT;
            int m = v / KQ, kq = v % KQ;
            cp16(smem_u32(&As[buf][m][kq * 4]),
                 &A[(size_t)(m0 + m) * lda + k0 + kq * 4]);
        }
        #pragma unroll
        for (int i = 0; i < LB; i++) {
            int v = tid + i * NT;
            int nq = v % (BN / 4), k = v / (BN / 4);
            cp16(smem_u32(&Bs[buf][k][nq * 4]),
                 &Bm[(size_t)(k0 + k) * ldb + n0 + nq * 4]);
        }
    };

    float acc[MT][NTL][4];
    #pragma unroll
    for (int i = 0; i < MT; i++)
        #pragma unroll
        for (int j = 0; j < NTL; j++)
            #pragma unroll
            for (int c = 0; c < 4; c++) acc[i][j][c] = 0.f;

    const int NI = K / BK;
    #pragma unroll
    for (int s = 0; s < STAGES - 1; s++) { issue(s, s * BK); cp_commit(); }

    int cur = 0;
    for (int i = 0; i < NI; i++) {
        cp_wait<STAGES - 2>();
        __syncthreads();
        int nx = i + STAGES - 1;
        if (nx < NI) issue(nx % STAGES, nx * BK);
        cp_commit();

        #pragma unroll
        for (int ks = 0; ks < BK; ks += 8) {
            float af[MT][4], bf[NTL][2];
            #pragma unroll
            for (int mt = 0; mt < MT; mt++) {
                int rb0 = warpM * WM + mt * 16;
                af[mt][0] = As[cur][rb0 + gid    ][ks + tig];
                af[mt][1] = As[cur][rb0 + gid + 8][ks + tig];
                af[mt][2] = As[cur][rb0 + gid    ][ks + tig + 4];
                af[mt][3] = As[cur][rb0 + gid + 8][ks + tig + 4];
            }
            #pragma unroll
            for (int nt = 0; nt < NTL; nt++) {
                int cb0 = warpN * WN + nt * 8;
                bf[nt][0] = Bs[cur][ks + tig    ][cb0 + gid];
                bf[nt][1] = Bs[cur][ks + tig + 4][cb0 + gid];
            }
            #pragma unroll
            for (int mt = 0; mt < MT; mt++)
                #pragma unroll
                for (int nt = 0; nt < NTL; nt++)
                    mma_tf32(acc[mt][nt][0], acc[mt][nt][1],
                             acc[mt][nt][2], acc[mt][nt][3],
                             af[mt][0], af[mt][1], af[mt][2], af[mt][3],
                             bf[nt][0], bf[nt][1]);
        }
        cur++; if (cur == STAGES) cur = 0;
    }

    #pragma unroll
    for (int mt = 0; mt < MT; mt++) {
        int row = m0 + warpM * WM + mt * 16 + gid;
        #pragma unroll
        for (int nt = 0; nt < NTL; nt++) {
            int col = n0 + warpN * WN + nt * 8 + tig * 2;
            float v0 = acc[mt][nt][0];
            float v1 = acc[mt][nt][1];
            float v2 = acc[mt][nt][2];
            float v3 = acc[mt][nt][3];
            if (bias) {
                float b0v = bias[col], b1v = bias[col + 1];
                v0 += b0v; v1 += b1v; v2 += b0v; v3 += b1v;
            }
            if (ACT == 1) {
                v0 = gelu_exact(v0); v1 = gelu_exact(v1);
                v2 = gelu_exact(v2); v3 = gelu_exact(v3);
            }
            *(float2*)&C[(size_t)row * ldc + col]       = make_float2(v0, v1);
            *(float2*)&C[(size_t)(row + 8) * ldc + col] = make_float2(v2, v3);
        }
    }
}

constexpr int gemm7_smem(int BM, int BN, int BK, int S) {
    return (S * BM * (BK + 4) + S * BK * (BN + 8)) * 4;
}

// ---------------- thin GEMM: 64x128, BK=16, 256 thr, C-prefetch --------------
// X(tile) = (GATED? gate*X : X) + A @ B + bias; colsum -> meanp2.
#define TSTG 3
constexpr int thin2_smem() {
    return (TSTG * 64 * 20 + TSTG * 16 * 136 + 64 * 132) * 4;   // 75264
}

template<int GATED>
__global__ __launch_bounds__(256)
void gemm_thin_k(const float* __restrict__ A, int lda,
                 const float* __restrict__ Bm, int ldb,
                 float* __restrict__ C, int ldc,
                 const float* __restrict__ bias, int K,
                 float* __restrict__ meanp2,
                 const float* __restrict__ gateIn)
{
    constexpr int BM = 64, BN = 128, BK = 16;
    constexpr int MT = 2, NTL = 4;
    constexpr int SA = 20, SB = 136, SC = 132;

    extern __shared__ float smemf[];
    float (*As)[BM][SA] = reinterpret_cast<float(*)[BM][SA]>(smemf);
    float (*Bs)[BK][SB] = reinterpret_cast<float(*)[BK][SB]>(smemf + TSTG * BM * SA);
    float* Cs = smemf + TSTG * BM * SA + TSTG * BK * SB;
    __shared__ float scred[8][128];
    __shared__ float gg[128];

    const int m0 = blockIdx.y * BM;
    const int n0 = blockIdx.x * BN;
    const int tid   = threadIdx.x;
    const int warp  = tid >> 5;
    const int lane  = tid & 31;
    const int gid   = lane >> 2;
    const int tig   = lane & 3;
    const int warpM = warp >> 2;
    const int warpN = warp & 3;

    // prefetch C tile (residual) — first commit group
    #pragma unroll
    for (int i = 0; i < 8; i++) {
        int v = tid + i * 256;
        int r = v >> 5, c4 = v & 31;
        cp16(smem_u32(&Cs[r * SC + c4 * 4]),
             &C[(size_t)(m0 + r) * ldc + n0 + c4 * 4]);
    }
    cp_commit();

    if (GATED) {
        int batch = blockIdx.y >> 4;     // 64 rows/tile, 1024 rows/batch
        if (tid < 128) gg[tid] = gateIn[batch * D_ + n0 + tid];
    }

    auto issue = [&](int buf, int k0) {
        {
            int m = tid >> 2, kq = tid & 3;
            cp16(smem_u32(&As[buf][m][kq * 4]),
                 &A[(size_t)(m0 + m) * lda + k0 + kq * 4]);
        }
        #pragma unroll
        for (int i = 0; i < 2; i++) {
            int v = tid + i * 256;
            int k = v >> 5, nq = v & 31;
            cp16(smem_u32(&Bs[buf][k][nq * 4]),
                 &Bm[(size_t)(k0 + k) * ldb + n0 + nq * 4]);
        }
    };

    float acc[MT][NTL][4];
    #pragma unroll
    for (int i = 0; i < MT; i++)
        #pragma unroll
        for (int j = 0; j < NTL; j++)
            #pragma unroll
            for (int c = 0; c < 4; c++) acc[i][j][c] = 0.f;

    const int NI = K / BK;
    #pragma unroll
    for (int s = 0; s < TSTG - 1; s++) { issue(s, s * BK); cp_commit(); }

    int cur = 0;
    for (int i = 0; i < NI; i++) {
        cp_wait<TSTG - 2>();
        __syncthreads();
        int nx = i + TSTG - 1;
        if (nx < NI) issue(nx % TSTG, nx * BK);
        cp_commit();

        #pragma unroll
        for (int ks = 0; ks < BK; ks += 8) {
            float af[MT][4], bf[NTL][2];
            #pragma unroll
            for (int mt = 0; mt < MT; mt++) {
                int rb0 = warpM * 32 + mt * 16;
                af[mt][0] = As[cur][rb0 + gid    ][ks + tig];
                af[mt][1] = As[cur][rb0 + gid + 8][ks + tig];
                af[mt][2] = As[cur][rb0 + gid    ][ks + tig + 4];
                af[mt][3] = As[cur][rb0 + gid + 8][ks + tig + 4];
            }
            #pragma unroll
            for (int nt = 0; nt < NTL; nt++) {
                int cb0 = warpN * 32 + nt * 8;
                bf[nt][0] = Bs[cur][ks + tig    ][cb0 + gid];
                bf[nt][1] = Bs[cur][ks + tig + 4][cb0 + gid];
            }
            #pragma unroll
            for (int mt = 0; mt < MT; mt++)
                #pragma unroll
                for (int nt = 0; nt < NTL; nt++)
                    mma_tf32(acc[mt][nt][0], acc[mt][nt][1],
                             acc[mt][nt][2], acc[mt][nt][3],
                             af[mt][0], af[mt][1], af[mt][2], af[mt][3],
                             bf[nt][0], bf[nt][1]);
        }
        cur++; if (cur == TSTG) cur = 0;
    }

    // stage acc + bias + (gated) residual into Cs
    #pragma unroll
    for (int mt = 0; mt < MT; mt++) {
        int lr = warpM * 32 + mt * 16 + gid;
        #pragma unroll
        for (int nt = 0; nt < NTL; nt++) {
            int lc = warpN * 32 + nt * 8 + tig * 2;
            float b0v = bias[n0 + lc], b1v = bias[n0 + lc + 1];
            float2 c0 = *(float2*)&Cs[lr * SC + lc];
            float2 c1 = *(float2*)&Cs[(lr + 8) * SC + lc];
            if (GATED) {
                float g0 = gg[lc], g1 = gg[lc + 1];
                c0.x *= g0; c0.y *= g1; c1.x *= g0; c1.y *= g1;
            }
            *(float2*)&Cs[lr * SC + lc] =
                make_float2(acc[mt][nt][0] + b0v + c0.x, acc[mt][nt][1] + b1v + c0.y);
            *(float2*)&Cs[(lr + 8) * SC + lc] =
                make_float2(acc[mt][nt][2] + b0v + c1.x, acc[mt][nt][3] + b1v + c1.y);
        }
    }
    __syncthreads();

    // coalesced float4 writeback + column partial sums
    int c4 = tid & 31, rg = tid >> 5;
    float cs0 = 0.f, cs1 = 0.f, cs2 = 0.f, cs3 = 0.f;
    #pragma unroll
    for (int i = 0; i < 8; i++) {
        int r = rg * 8 + i;
        float4 t = *(float4*)&Cs[r * SC + c4 * 4];
        cs0 += t.x; cs1 += t.y; cs2 += t.z; cs3 += t.w;
        *(float4*)&C[(size_t)(m0 + r) * ldc + n0 + c4 * 4] = t;
    }
    *(float4*)&scred[rg][c4 * 4] = make_float4(cs0, cs1, cs2, cs3);
    __syncthreads();
    if (tid < 128) {
        float s = 0.f;
        #pragma unroll
        for (int g = 0; g < 8; g++) s += scred[g][tid];
        meanp2[(size_t)blockIdx.y * 256 + n0 + tid] = s;
    }
}

// ---------------- fused copy + layernorm (float4, 4 rows/CTA) ----------------
__global__ void copy_ln_k(const float4* __restrict__ xin, float4* __restrict__ X,
                          const float* __restrict__ g, const float* __restrict__ b,
                          float4* __restrict__ out)
{
    int tid = threadIdx.x;
    int rib = tid >> 6, t64 = tid & 63;
    int row = blockIdx.x * 4 + rib;
    int idx = row * 64 + t64;
    int lane = tid & 31, wir = (tid >> 5) & 1;
    __shared__ float r1[4][2], r2[4][2];

    float4 v = xin[idx];
    X[idx] = v;
    float s  = v.x + v.y + v.z + v.w;
    float s2 = v.x*v.x + v.y*v.y + v.z*v.z + v.w*v.w;
    #pragma unroll
    for (int m = 16; m > 0; m >>= 1) {
        s  += __shfl_xor_sync(0xffffffff, s, m);
        s2 += __shfl_xor_sync(0xffffffff, s2, m);
    }
    if (lane == 0) { r1[rib][wir] = s; r2[rib][wir] = s2; }
    __syncthreads();
    float ts = r1[rib][0] + r1[rib][1], ts2 = r2[rib][0] + r2[rib][1];
    float mu = ts * (1.f / D_);
    float var = ts2 * (1.f / D_) - mu * mu;
    float rs = rsqrtf(var + EPS_);
    float4 gg = *(const float4*)&g[t64 * 4];
    float4 bb = *(const float4*)&b[t64 * 4];
    float4 o;
    o.x = (v.x - mu) * rs * gg.x + bb.x;
    o.y = (v.y - mu) * rs * gg.y + bb.y;
    o.z = (v.z - mu) * rs * gg.z + bb.z;
    o.w = (v.w - mu) * rs * gg.w + bb.w;
    out[idx] = o;
}

// ------- virtual scale + layernorm: reads gate, does NOT write X -------------
__global__ void scale_ln_k(const float4* __restrict__ X, const float* __restrict__ gate,
                           const float* __restrict__ g, const float* __restrict__ b,
                           float4* __restrict__ out)
{
    int tid = threadIdx.x;
    int rib = tid >> 6, t64 = tid & 63;
    int row = blockIdx.x * 4 + rib;
    int bbatch = row >> 10;
    int idx = row * 64 + t64;
    int lane = tid & 31, wir = (tid >> 5) & 1;
    __shared__ float r1[4][2], r2[4][2];

    float4 gv = *(const float4*)&gate[bbatch * D_ + t64 * 4];
    float4 v = X[idx];
    v.x *= gv.x; v.y *= gv.y; v.z *= gv.z; v.w *= gv.w;
    float s  = v.x + v.y + v.z + v.w;
    float s2 = v.x*v.x + v.y*v.y + v.z*v.z + v.w*v.w;
    #pragma unroll
    for (int m = 16; m > 0; m >>= 1) {
        s  += __shfl_xor_sync(0xffffffff, s, m);
        s2 += __shfl_xor_sync(0xffffffff, s2, m);
    }
    if (lane == 0) { r1[rib][wir] = s; r2[rib][wir] = s2; }
    __syncthreads();
    float ts = r1[rib][0] + r1[rib][1], ts2 = r2[rib][0] + r2[rib][1];
    float mu = ts * (1.f / D_);
    float var = ts2 * (1.f / D_) - mu * mu;
    float rs = rsqrtf(var + EPS_);
    float4 gg = *(const float4*)&g[t64 * 4];
    float4 bb = *(const float4*)&b[t64 * 4];
    float4 o;
    o.x = (v.x - mu) * rs * gg.x + bb.x;
    o.y = (v.y - mu) * rs * gg.y + bb.y;
    o.z = (v.z - mu) * rs * gg.z + bb.z;
    o.w = (v.w - mu) * rs * gg.w + bb.w;
    out[idx] = o;
}

// SE gate: s = sigmoid(relu(mean @ w1) @ w2); one block per batch
__global__ void gate_k(const float* __restrict__ meanp2, const float* __restrict__ w1,
                       const float* __restrict__ w2, float* __restrict__ gatebuf)
{
    int b = blockIdx.x, tid = threadIdx.x;
    __shared__ float m[D_];
    __shared__ float t[D_ / 4];
    float acc0 = 0.f;
    #pragma unroll
    for (int i = 0; i < 16; i++)
        acc0 += meanp2[((size_t)(b * 16 + i)) * 256 + tid];
    m[tid] = acc0 * (1.f / N_);
    __syncthreads();
    if (tid < D_ / 4) {
        float acc = 0.f;
        #pragma unroll 8
        for (int d = 0; d < D_; d++) acc += m[d] * w1[d * (D_ / 4) + tid];
        t[tid] = fmaxf(acc, 0.f);
    }
    __syncthreads();
    float acc = 0.f;
    #pragma unroll 8
    for (int j = 0; j < D_ / 4; j++) acc += t[j] * w2[j * D_ + tid];
    gatebuf[b * D_ + tid] = 1.f / (1.f + expf(-acc));
}

__global__ void scale_k(float4* __restrict__ x, const float* __restrict__ gate)
{
    int idx = blockIdx.x * 256 + threadIdx.x;
    int d4 = idx & (D_ / 4 - 1);
    int b = idx / (N_ * D_ / 4);
    const float4 gv = *(const float4*)&gate[b * D_ + d4 * 4];
    float4 v = x[idx];
    v.x *= gv.x; v.y *= gv.y; v.z *= gv.z; v.w *= gv.w;
    x[idx] = v;
}

// depthwise 1x3 conv + center-tap + BN(eval) + exact gelu (float4)
__global__ void conv_k(const float4* __restrict__ y, const float* __restrict__ wh,
                       const float* __restrict__ bh, const float* __restrict__ wv,
                       const float* __restrict__ bv, const float* __restrict__ bng,
                       const float* __restrict__ bnb, const float* __restrict__ bnm,
                       const float* __restrict__ bnv, float4* __restrict__ out)
{
    int idx = blockIdx.x * 256 + threadIdx.x;
    int m4 = idx & (M_ / 4 - 1);
    int n = (idx / (M_ / 4)) & (N_ - 1);
    int m = m4 * 4;
    float4 y0 = y[idx];
    float4 ym = (n > 0)      ? y[idx - M_ / 4] : make_float4(0.f, 0.f, 0.f, 0.f);
    float4 yp = (n < N_ - 1) ? y[idx + M_ / 4] : make_float4(0.f, 0.f, 0.f, 0.f);
    float r[4];
    float y0a[4] = {y0.x, y0.y, y0.z, y0.w};
    float yma[4] = {ym.x, ym.y, ym.z, ym.w};
    float ypa[4] = {yp.x, yp.y, yp.z, yp.w};
    #pragma unroll
    for (int j = 0; j < 4; j++) {
        int mm = m + j;
        float ch = wh[mm * 3 + 0] * yma[j] + wh[mm * 3 + 1] * y0a[j]
                 + wh[mm * 3 + 2] * ypa[j] + bh[mm];
        float cv = wv[mm * 3 + 1] * y0a[j] + bv[mm];
        float zz = ch + cv;
        zz = (zz - bnm[mm]) * rsqrtf(bnv[mm] + EPS_) * bng[mm] + bnb[mm];
        r[j] = gelu_exact(zz);
    }
    out[idx] = make_float4(r[0], r[1], r[2], r[3]);
}

// ---------------- driver -----------------------------------------------------
extern "C" void kernel_launch(void* const* d_in, const int* in_sizes, int n_in,
                              void* d_out, int out_size)
{
    const float* x_in  = (const float*)d_in[0];
    const float* ln1_g = (const float*)d_in[1];
    const float* ln1_b = (const float*)d_in[2];
    const float* w_qkv = (const float*)d_in[3];
    const float* w_out = (const float*)d_in[4];
    const float* b_out = (const float*)d_in[5];
    const float* ln2_g = (const float*)d_in[6];
    const float* ln2_b = (const float*)d_in[7];
    const float* w_fc1 = (const float*)d_in[8];
    const float* b_fc1 = (const float*)d_in[9];
    const float* wh    = (const float*)d_in[10];
    const float* bh    = (const float*)d_in[11];
    const float* wv    = (const float*)d_in[12];
    const float* bv    = (const float*)d_in[13];
    const float* bn_g  = (const float*)d_in[14];
    const float* bn_b  = (const float*)d_in[15];
    const float* bn_m  = (const float*)d_in[16];
    const float* bn_v  = (const float*)d_in[17];
    const float* w_fc2 = (const float*)d_in[18];
    const float* b_fc2 = (const float*)d_in[19];
    const float* ls_w1 = (const float*)d_in[20];
    const float* ls_w2 = (const float*)d_in[21];

    float *ph, *pqkv, *po, *pt1, *pt2, *pmeanp2, *pgate;
    cudaGetSymbolAddress((void**)&ph,      g_h);
    cudaGetSymbolAddress((void**)&pqkv,    g_qkv);
    cudaGetSymbolAddress((void**)&po,      g_o);
    cudaGetSymbolAddress((void**)&pt1,     g_t1);
    cudaGetSymbolAddress((void**)&pt2,     g_t2);
    cudaGetSymbolAddress((void**)&pmeanp2, g_meanp2);
    cudaGetSymbolAddress((void**)&pgate,   g_gate);

    constexpr int SM_BIG  = gemm7_smem(128, 128, 16, 3);   // 56832
    constexpr int SM_THIN = thin2_smem();                  // 75264

    cudaFuncSetAttribute(flash_k, cudaFuncAttributeMaxDynamicSharedMemorySize,
                         FLASH_SMEM_BYTES);
    cudaFuncSetAttribute(gemm7_k<128,128,16,2,4,0,3>,
                         cudaFuncAttributeMaxDynamicSharedMemorySize, SM_BIG);
    cudaFuncSetAttribute(gemm7_k<128,128,16,2,4,1,3>,
                         cudaFuncAttributeMaxDynamicSharedMemorySize, SM_BIG);
    cudaFuncSetAttribute(gemm_thin_k<0>,
                         cudaFuncAttributeMaxDynamicSharedMemorySize, SM_THIN);
    cudaFuncSetAttribute(gemm_thin_k<1>,
                         cudaFuncAttributeMaxDynamicSharedMemorySize, SM_THIN);

    float* X = (float*)d_out;
    const int ROWS = B_ * N_;   // 8192

    for (int l = 0; l < 2; l++) {
        const float* w_qkv_l = w_qkv + (size_t)l * D_ * 3 * D_;
        const float* w_out_l = w_out + (size_t)l * D_ * D_;
        const float* b_out_l = b_out + (size_t)l * D_;
        const float* w_fc1_l = w_fc1 + (size_t)l * D_ * M_;
        const float* b_fc1_l = b_fc1 + (size_t)l * M_;
        const float* w_fc2_l = w_fc2 + (size_t)l * M_ * D_;
        const float* b_fc2_l = b_fc2 + (size_t)l * D_;
        const float* w1_l    = ls_w1 + (size_t)l * D_ * (D_/4);
        const float* w2_l    = ls_w2 + (size_t)l * (D_/4) * D_;

        // --- MHSA ---  (h = LN1(X); layer 0 fuses the initial copy;
        //                l>0: h was produced by the virtual scale_ln below)
        if (l == 0)
            copy_ln_k<<<ROWS/4, 256>>>((const float4*)x_in, (float4*)X,
                                       ln1_g, ln1_b, (float4*)ph);

        // qkv = h @ w_qkv
        gemm7_k<128,128,16,2,4,0,3><<<dim3((3*D_)/128, ROWS/128, 1), 256, SM_BIG>>>(
            ph, D_, w_qkv_l, 3*D_, pqkv, 3*D_, nullptr, D_);

        // fused attention
        flash_k<<<dim3(1, N_/FBM, B_*H_), 128, FLASH_SMEM_BYTES>>>(pqkv, po);

        // lsrc #1: X = (gate_prev * X) + o@w_out + b_out; colsum -> meanp2
        if (l == 0)
            gemm_thin_k<0><<<dim3(D_/128, ROWS/64, 1), 256, SM_THIN>>>(
                po, D_, w_out_l, D_, X, D_, b_out_l, D_, pmeanp2, nullptr);
        else
            gemm_thin_k<1><<<dim3(D_/128, ROWS/64, 1), 256, SM_THIN>>>(
                po, D_, w_out_l, D_, X, D_, b_out_l, D_, pmeanp2, pgate);

        gate_k<<<B_, 256>>>(pmeanp2, w1_l, w2_l, pgate);

        // h = LN2(gate * X)   (X stays unscaled in memory)
        scale_ln_k<<<ROWS/4, 256>>>((const float4*)X, pgate,
                                    ln2_g + l * D_, ln2_b + l * D_, (float4*)ph);

        // --- MLP ---
        gemm7_k<128,128,16,2,4,1,3><<<dim3(M_/128, ROWS/128, 1), 256, SM_BIG>>>(
            ph, D_, w_fc1_l, M_, pt1, M_, b_fc1_l, D_);

        conv_k<<<(B_*N_*M_)/1024, 256>>>(
            (const float4*)pt1, wh + (size_t)l*M_*3, bh + (size_t)l*M_,
            wv + (size_t)l*M_*3, bv + (size_t)l*M_,
            bn_g + (size_t)l*M_, bn_b + (size_t)l*M_,
            bn_m + (size_t)l*M_, bn_v + (size_t)l*M_, (float4*)pt2);

        // lsrc #2: X = (gate * X) + t2@w_fc2 + b_fc2; colsum -> meanp2
        gemm_thin_k<1><<<dim3(D_/128, ROWS/64, 1), 256, SM_THIN>>>(
            pt2, M_, w_fc2_l, D_, X, D_, b_fc2_l, M_, pmeanp2, pgate);

        gate_k<<<B_, 256>>>(pmeanp2, w1_l, w2_l, pgate);

        if (l + 1 < 2)
            scale_ln_k<<<ROWS/4, 256>>>((const float4*)X, pgate,
                                        ln1_g + (l+1) * D_, ln1_b + (l+1) * D_,
                                        (float4*)ph);
        else
            scale_k<<<(B_*N_*D_)/1024, 256>>>((float4*)X, pgate);
    }
}